// round 6
// baseline (speedup 1.0000x reference)
#include <cuda_runtime.h>
#include <cstdint>

// CausalAttentionProduct — flash attention, tf32 mma.sync, no-max softmax.
// R6: BM=64 (4 CTA/SM), per-thread l accumulator (no per-tile reductions,
// no O rescale), P truncated to tf32 via LOP3 so lsum and PV agree exactly.
// B=2, H=12, S=4096, D=64. 4 warps; each warp owns one m16 tile.
// Reference quirk: scores[..., -128:, -128:] OVERWRITTEN with (0 if k<=q else -inf).

#define NB 2
#define NH 12
#define S_LEN 4096
#define DH 64
#define BM 64
#define BN 64
#define LOG2E 1.4426950408889634f
#define SHIFT 16.0f
#define P_ONE 1.52587890625e-05f   // 2^-16 (exact in tf32)

#define QS_PITCH 68
#define KS_PITCH 68
#define VS_PITCH 72
#define OFF_QS 0
#define OFF_KS (OFF_QS + BM * QS_PITCH)   //  4352
#define OFF_VS (OFF_KS + BN * KS_PITCH)   //  8704
#define OFF_MK (OFF_VS + BN * VS_PITCH)   // 13312
#define SMEM_FLOATS (OFF_MK + BN)         // 13376
#define SMEM_BYTES (SMEM_FLOATS * 4)      // 53504 B -> 4 CTA/SM

extern __shared__ float smem[];

__device__ __forceinline__ float f2tf(float x) {
    uint32_t r;
    asm("cvt.rna.tf32.f32 %0, %1;" : "=r"(r) : "f"(x));
    return __uint_as_float(r);
}
__device__ __forceinline__ float tftrunc(float x) {   // RZ to tf32, 1 LOP
    return __uint_as_float(__float_as_uint(x) & 0xFFFFE000u);
}
__device__ __forceinline__ float ex2(float x) {
    float r;
    asm("ex2.approx.ftz.f32 %0, %1;" : "=f"(r) : "f"(x));
    return r;
}
__device__ __forceinline__ void mma_tf32(float c[4],
                                         float a0, float a1, float a2, float a3,
                                         float b0, float b1) {
    asm volatile(
        "mma.sync.aligned.m16n8k8.row.col.f32.tf32.tf32.f32 "
        "{%0,%1,%2,%3}, {%4,%5,%6,%7}, {%8,%9}, {%0,%1,%2,%3};"
        : "+f"(c[0]), "+f"(c[1]), "+f"(c[2]), "+f"(c[3])
        : "r"(__float_as_uint(a0)), "r"(__float_as_uint(a1)),
          "r"(__float_as_uint(a2)), "r"(__float_as_uint(a3)),
          "r"(__float_as_uint(b0)), "r"(__float_as_uint(b1)));
}

__global__ void __launch_bounds__(128, 4)
attn_tf32_kernel(const float* __restrict__ Q,
                 const float* __restrict__ K,
                 const float* __restrict__ V,
                 const float* __restrict__ mask,
                 float* __restrict__ O)
{
    float* Qs = smem + OFF_QS;
    float* Ks = smem + OFF_KS;
    float* Vs = smem + OFF_VS;
    float* mk = smem + OFF_MK;

    const int tid  = threadIdx.x;
    const int warp = tid >> 5;
    const int lane = tid & 31;
    const int g    = lane >> 2;   // 0..7
    const int tg   = lane & 3;    // 0..3

    const int bh    = blockIdx.y;
    const int b     = bh / NH;
    const int qbase = blockIdx.x * BM;
    const bool qsp  = (qbase >= S_LEN - 128);   // last two q tiles are special

    const float* Qp = Q + (size_t)bh * S_LEN * DH;
    const float* Kp = K + (size_t)bh * S_LEN * DH;
    const float* Vp = V + (size_t)bh * S_LEN * DH;
    const float* Mp = mask + (size_t)b * S_LEN;
    float* Op = O + (size_t)bh * S_LEN * DH;

    // quad-shuffle constants for c->a fragment exchange
    const int qbl = (lane & 28) | (tg >> 1);
    const bool podd = (tg & 1);

    // ---- load Q tile (scale folded, tf32 pre-converted) ----
    {
        const float qscale = 0.125f * LOG2E;
        const int r0 = tid >> 4;
        const int c4 = tid & 15;
        #pragma unroll
        for (int i = 0; i < 8; i++) {
            int m = r0 + 8 * i;
            float4 v = *(const float4*)(Qp + (size_t)(qbase + m) * DH + c4 * 4);
            float4 w = make_float4(f2tf(v.x * qscale), f2tf(v.y * qscale),
                                   f2tf(v.z * qscale), f2tf(v.w * qscale));
            *(float4*)(Qs + m * QS_PITCH + c4 * 4) = w;
        }
    }

    float lsum[2] = {0.0f, 0.0f};
    float oacc[8][4];
    #pragma unroll
    for (int nt = 0; nt < 8; nt++)
        #pragma unroll
        for (int j = 0; j < 4; j++) oacc[nt][j] = 0.0f;

    const int wrow = warp * 16;
    const int qrow0 = qbase + wrow + g;        // row for j=0,1 (rh=0)

    for (int kt = 0; kt < S_LEN / BN; kt++) {
        const int kbase = kt * BN;

        __syncthreads();

        // ---- stage K, V (tf32 pre-converted) + mask chunk ----
        {
            const int r0 = tid >> 4;
            const int c4 = tid & 15;
            #pragma unroll
            for (int i = 0; i < 4; i++) {
                int n = r0 + 8 * (2 * i + (c4 >> 3));   // split halves to spread
                (void)n;
            }
            #pragma unroll
            for (int i = 0; i < 8; i++) {
                int n = r0 + 8 * i;
                float4 kv = *(const float4*)(Kp + (size_t)(kbase + n) * DH + c4 * 4);
                float4 kw = make_float4(f2tf(kv.x), f2tf(kv.y), f2tf(kv.z), f2tf(kv.w));
                *(float4*)(Ks + n * KS_PITCH + c4 * 4) = kw;
                float4 vv = *(const float4*)(Vp + (size_t)(kbase + n) * DH + c4 * 4);
                float4 vw = make_float4(f2tf(vv.x), f2tf(vv.y), f2tf(vv.z), f2tf(vv.w));
                *(float4*)(Vs + n * VS_PITCH + c4 * 4) = vw;
            }
            if (tid < 16) {
                float4 mv = *(const float4*)(Mp + kbase + tid * 4);
                mv.x = mv.x * LOG2E - SHIFT;
                mv.y = mv.y * LOG2E - SHIFT;
                mv.z = mv.z * LOG2E - SHIFT;
                mv.w = mv.w * LOG2E - SHIFT;
                *(float4*)(mk + tid * 4) = mv;
            }
        }
        __syncthreads();

        // ---- S = Q @ K^T ----
        float sacc[8][4];
        #pragma unroll
        for (int nt = 0; nt < 8; nt++)
            #pragma unroll
            for (int j = 0; j < 4; j++) sacc[nt][j] = 0.0f;

        #pragma unroll
        for (int ks = 0; ks < 8; ks++) {
            const float* qr = Qs + (wrow + g) * QS_PITCH + ks * 8;
            float a0 = qr[tg];
            float a1 = qr[8 * QS_PITCH + tg];
            float a2 = qr[tg + 4];
            float a3 = qr[8 * QS_PITCH + tg + 4];
            #pragma unroll
            for (int nt = 0; nt < 8; nt++) {
                const float* kr = Ks + (nt * 8 + g) * KS_PITCH + ks * 8;
                float b0 = kr[tg];
                float b1 = kr[tg + 4];
                mma_tf32(sacc[nt], a0, a1, a2, a3, b0, b1);
            }
        }

        // ---- softmax (no running max) -> p in sacc (tf32-truncated) ----
        if (qsp && kbase >= S_LEN - 128) {
            #pragma unroll
            for (int nt = 0; nt < 8; nt++)
                #pragma unroll
                for (int j = 0; j < 4; j++) {
                    int qg = qrow0 + (j >> 1) * 8;
                    int kg = kbase + nt * 8 + 2 * tg + (j & 1);
                    float p = (kg <= qg) ? P_ONE : 0.0f;
                    sacc[nt][j] = p;
                    lsum[j >> 1] += p;
                }
        } else {
            #pragma unroll
            for (int nt = 0; nt < 8; nt++) {
                float2 mv = *(const float2*)(mk + nt * 8 + 2 * tg);
                float p0 = tftrunc(ex2(sacc[nt][0] + mv.x));
                float p1 = tftrunc(ex2(sacc[nt][1] + mv.y));
                float p2 = tftrunc(ex2(sacc[nt][2] + mv.x));
                float p3 = tftrunc(ex2(sacc[nt][3] + mv.y));
                sacc[nt][0] = p0; sacc[nt][1] = p1;
                sacc[nt][2] = p2; sacc[nt][3] = p3;
                lsum[0] += p0 + p1;
                lsum[1] += p2 + p3;
            }
        }

        // ---- O += P @ V : a-frags via quad shuffle from sacc c-layout ----
        #pragma unroll
        for (int ks = 0; ks < 8; ks++) {
            float s0 = __shfl_sync(0xffffffffu, sacc[ks][0], qbl);
            float s1 = __shfl_sync(0xffffffffu, sacc[ks][1], qbl);
            float s2 = __shfl_sync(0xffffffffu, sacc[ks][2], qbl);
            float s3 = __shfl_sync(0xffffffffu, sacc[ks][3], qbl);
            float t0 = __shfl_sync(0xffffffffu, sacc[ks][0], qbl + 2);
            float t1 = __shfl_sync(0xffffffffu, sacc[ks][1], qbl + 2);
            float t2 = __shfl_sync(0xffffffffu, sacc[ks][2], qbl + 2);
            float t3 = __shfl_sync(0xffffffffu, sacc[ks][3], qbl + 2);
            float a0 = podd ? s1 : s0;   // row g,   k = tg
            float a1 = podd ? s3 : s2;   // row g+8, k = tg
            float a2 = podd ? t1 : t0;   // row g,   k = tg+4
            float a3 = podd ? t3 : t2;   // row g+8, k = tg+4
            #pragma unroll
            for (int nt = 0; nt < 8; nt++) {
                const float* vr = Vs + (ks * 8 + tg) * VS_PITCH + nt * 8 + g;
                float b0 = vr[0];
                float b1 = vr[4 * VS_PITCH];
                mma_tf32(oacc[nt], a0, a1, a2, a3, b0, b1);
            }
        }
    }

    // ---- final l reduction (over tg within quad) + epilogue ----
    #pragma unroll
    for (int rh = 0; rh < 2; rh++) {
        lsum[rh] += __shfl_xor_sync(0xffffffffu, lsum[rh], 1);
        lsum[rh] += __shfl_xor_sync(0xffffffffu, lsum[rh], 2);
    }
    #pragma unroll
    for (int rh = 0; rh < 2; rh++) {
        float inv = 1.0f / lsum[rh];
        size_t row = (size_t)(qbase + wrow + g + 8 * rh);
        #pragma unroll
        for (int nt = 0; nt < 8; nt++) {
            float2 ov = make_float2(oacc[nt][2 * rh] * inv,
                                    oacc[nt][2 * rh + 1] * inv);
            *(float2*)(Op + row * DH + nt * 8 + 2 * tg) = ov;
        }
    }
}

extern "C" void kernel_launch(void* const* d_in, const int* in_sizes, int n_in,
                              void* d_out, int out_size)
{
    (void)in_sizes; (void)n_in; (void)out_size;
    const float* Q    = (const float*)d_in[0];
    const float* K    = (const float*)d_in[1];
    const float* V    = (const float*)d_in[2];
    const float* mask = (const float*)d_in[3];
    float* O = (float*)d_out;

    cudaFuncSetAttribute(attn_tf32_kernel,
                         cudaFuncAttributeMaxDynamicSharedMemorySize, SMEM_BYTES);

    dim3 grid(S_LEN / BM, NB * NH);
    attn_tf32_kernel<<<grid, 128, SMEM_BYTES>>>(Q, K, V, mask, O);
}

// round 9
// speedup vs baseline: 1.3586x; 1.3586x over previous
#include <cuda_runtime.h>
#include <cuda_fp16.h>
#include <cstdint>

// CausalAttentionProduct — flash attention, fp16 mma.sync m16n8k16 + ldmatrix.
// R8 = R7 with staging-stride bugfix (uint2 stores at 8B stride, was 16B ->
// half of each smem row uninitialized -> NaN).
// fp16 datapath (same 10-bit mantissa as tf32), ldmatrix.x4 fragment loads,
// ldmatrix.trans for V (no transpose staging), register P->A pack (no shuffle),
// no-max softmax (SHIFT=14, all p fp16-normal). BM=128, BN=64, 4 warps.
// Reference quirk: scores[..., -128:, -128:] OVERWRITTEN with (0 if k<=q else -inf).

#define NB 2
#define NH 12
#define S_LEN 4096
#define DH 64
#define BM 128
#define BN 64
#define LOG2E 1.4426950408889634f
#define SHIFT 14.0f
#define P_ONE 6.103515625e-05f   // 2^-14, exact in fp16 (normal)

// half tiles, row pitch 144 bytes (72 halves; 64 data + 8 pad).
// 144 B -> rows 4 banks apart: each ldmatrix 8x8 tile covers all 32 banks once.
#define PITCHB 144
#define OFF_QS 0
#define OFF_KS (OFF_QS + BM * PITCHB)   // 18432
#define OFF_VS (OFF_KS + BN * PITCHB)   // 27648
#define OFF_MK (OFF_VS + BN * PITCHB)   // 36864 (fp32 mask, 64 floats)
#define SMEM_BYTES (OFF_MK + BN * 4)    // 37120 B

extern __shared__ char smem_c[];

__device__ __forceinline__ float ex2(float x) {
    float r;
    asm("ex2.approx.ftz.f32 %0, %1;" : "=f"(r) : "f"(x));
    return r;
}
__device__ __forceinline__ uint32_t s2u(const void* p) {
    uint32_t a;
    asm("{ .reg .u64 t; cvta.to.shared.u64 t, %1; cvt.u32.u64 %0, t; }"
        : "=r"(a) : "l"(p));
    return a;
}
__device__ __forceinline__ uint32_t packh2(float lo, float hi) {
    __half2 h = __floats2half2_rn(lo, hi);
    return *(uint32_t*)&h;
}
__device__ __forceinline__ void ldmx4(uint32_t r[4], uint32_t addr) {
    asm volatile("ldmatrix.sync.aligned.m8n8.x4.shared.b16 {%0,%1,%2,%3}, [%4];"
                 : "=r"(r[0]), "=r"(r[1]), "=r"(r[2]), "=r"(r[3]) : "r"(addr));
}
__device__ __forceinline__ void ldmx4t(uint32_t r[4], uint32_t addr) {
    asm volatile("ldmatrix.sync.aligned.m8n8.x4.trans.shared.b16 {%0,%1,%2,%3}, [%4];"
                 : "=r"(r[0]), "=r"(r[1]), "=r"(r[2]), "=r"(r[3]) : "r"(addr));
}
__device__ __forceinline__ void mma16(float c[4],
                                      uint32_t a0, uint32_t a1, uint32_t a2, uint32_t a3,
                                      uint32_t b0, uint32_t b1) {
    asm volatile(
        "mma.sync.aligned.m16n8k16.row.col.f32.f16.f16.f32 "
        "{%0,%1,%2,%3}, {%4,%5,%6,%7}, {%8,%9}, {%0,%1,%2,%3};"
        : "+f"(c[0]), "+f"(c[1]), "+f"(c[2]), "+f"(c[3])
        : "r"(a0), "r"(a1), "r"(a2), "r"(a3), "r"(b0), "r"(b1));
}

__global__ void __launch_bounds__(128, 3)
attn_fp16_kernel(const float* __restrict__ Q,
                 const float* __restrict__ K,
                 const float* __restrict__ V,
                 const float* __restrict__ mask,
                 float* __restrict__ O)
{
    const int tid  = threadIdx.x;
    const int warp = tid >> 5;
    const int lane = tid & 31;
    const int g    = lane >> 2;
    const int tg   = lane & 3;

    const uint32_t sb = s2u(smem_c);
    float* mk = (float*)(smem_c + OFF_MK);

    const int bh    = blockIdx.y;
    const int b     = bh / NH;
    const int qbase = blockIdx.x * BM;
    const bool qsp  = (qbase == S_LEN - BM);

    const float* Qp = Q + (size_t)bh * S_LEN * DH;
    const float* Kp = K + (size_t)bh * S_LEN * DH;
    const float* Vp = V + (size_t)bh * S_LEN * DH;
    const float* Mp = mask + (size_t)b * S_LEN;
    float* Op = O + (size_t)bh * S_LEN * DH;

    const int wrow = warp * 32;

    // ---- ldmatrix lane-address bases ----
    const int lt = lane;
    const int t4 = lt >> 3;             // tile index 0..3
    // QK A: tiles (m0-7,k0-7),(m8-15,k0-7),(m0-7,k8-15),(m8-15,k8-15)
    const uint32_t qa_base = sb + OFF_QS
        + (uint32_t)(wrow + (lt & 7) + ((t4 & 1) * 8)) * PITCHB
        + (uint32_t)((t4 >> 1) * 16);                  // +at*16*PITCHB +ks*32
    // QK B: tiles (n0-7,k0-7),(n0-7,k8-15),(n8-15,k0-7),(n8-15,k8-15)
    const uint32_t kb_base = sb + OFF_KS
        + (uint32_t)(((t4 >> 1) * 8) + (lt & 7)) * PITCHB
        + (uint32_t)((t4 & 1) * 16);                   // +ntp*16*PITCHB +ks*32
    // PV B (trans): tiles (k0-7,n0-7),(k8-15,n0-7),(k0-7,n8-15),(k8-15,n8-15)
    const uint32_t vb_base = sb + OFF_VS
        + (uint32_t)(((t4 & 1) * 8) + (lt & 7)) * PITCHB
        + (uint32_t)((t4 >> 1) * 16);                  // +ks*16*PITCHB +ntp*32

    // ---- stage Q (scaled, fp16) ----
    {
        const float qs = 0.125f * LOG2E;
        const int ch = tid & 1;
        const int r0 = tid >> 1;
        #pragma unroll
        for (int j = 0; j < 2; j++) {
            int m = r0 + 64 * j;
            const float4* src = (const float4*)(Qp + (size_t)(qbase + m) * DH + ch * 32);
            char* dst = smem_c + OFF_QS + m * PITCHB + ch * 64;
            #pragma unroll
            for (int i = 0; i < 8; i++) {
                float4 v = src[i];
                uint2 u = make_uint2(packh2(v.x * qs, v.y * qs),
                                     packh2(v.z * qs, v.w * qs));
                *(uint2*)(dst + 8 * i) = u;
            }
        }
    }

    float lsum[2][2] = {{0.f, 0.f}, {0.f, 0.f}};
    float oacc[2][8][4];
    #pragma unroll
    for (int at = 0; at < 2; at++)
        #pragma unroll
        for (int nt = 0; nt < 8; nt++)
            #pragma unroll
            for (int j = 0; j < 4; j++) oacc[at][nt][j] = 0.f;

    for (int kt = 0; kt < S_LEN / BN; kt++) {
        const int kbase = kt * BN;

        __syncthreads();

        // ---- stage K, V (fp16) + mask chunk ----
        {
            const int ch = tid & 1;
            const int r0 = tid >> 1;
            const float4* ks_src = (const float4*)(Kp + (size_t)(kbase + r0) * DH + ch * 32);
            const float4* vs_src = (const float4*)(Vp + (size_t)(kbase + r0) * DH + ch * 32);
            char* kdst = smem_c + OFF_KS + r0 * PITCHB + ch * 64;
            char* vdst = smem_c + OFF_VS + r0 * PITCHB + ch * 64;
            #pragma unroll
            for (int i = 0; i < 8; i++) {
                float4 kv = ks_src[i];
                *(uint2*)(kdst + 8 * i) = make_uint2(packh2(kv.x, kv.y), packh2(kv.z, kv.w));
                float4 vv = vs_src[i];
                *(uint2*)(vdst + 8 * i) = make_uint2(packh2(vv.x, vv.y), packh2(vv.z, vv.w));
            }
            if (tid < 16) {
                float4 mv = *(const float4*)(Mp + kbase + tid * 4);
                mv.x = mv.x * LOG2E - SHIFT;
                mv.y = mv.y * LOG2E - SHIFT;
                mv.z = mv.z * LOG2E - SHIFT;
                mv.w = mv.w * LOG2E - SHIFT;
                *(float4*)(mk + tid * 4) = mv;
            }
        }
        __syncthreads();

        // ---- S = Q @ K^T  (4 k16-steps) ----
        float sacc[2][8][4];
        #pragma unroll
        for (int at = 0; at < 2; at++)
            #pragma unroll
            for (int nt = 0; nt < 8; nt++)
                #pragma unroll
                for (int j = 0; j < 4; j++) sacc[at][nt][j] = 0.f;

        #pragma unroll
        for (int ks = 0; ks < 4; ks++) {
            uint32_t a[2][4];
            ldmx4(a[0], qa_base + ks * 32);
            ldmx4(a[1], qa_base + 16 * PITCHB + ks * 32);
            #pragma unroll
            for (int ntp = 0; ntp < 4; ntp++) {
                uint32_t bm[4];
                ldmx4(bm, kb_base + (uint32_t)(ntp * 16 * PITCHB) + ks * 32);
                mma16(sacc[0][2 * ntp],     a[0][0], a[0][1], a[0][2], a[0][3], bm[0], bm[1]);
                mma16(sacc[0][2 * ntp + 1], a[0][0], a[0][1], a[0][2], a[0][3], bm[2], bm[3]);
                mma16(sacc[1][2 * ntp],     a[1][0], a[1][1], a[1][2], a[1][3], bm[0], bm[1]);
                mma16(sacc[1][2 * ntp + 1], a[1][0], a[1][1], a[1][2], a[1][3], bm[2], bm[3]);
            }
        }

        // ---- softmax (no running max): p = exp2(s + mask*log2e - 14) ----
        if (qsp && kbase >= S_LEN - 128) {
            #pragma unroll
            for (int at = 0; at < 2; at++)
                #pragma unroll
                for (int nt = 0; nt < 8; nt++)
                    #pragma unroll
                    for (int j = 0; j < 4; j++) {
                        int qg = qbase + wrow + at * 16 + g + (j >> 1) * 8;
                        int kg = kbase + nt * 8 + 2 * tg + (j & 1);
                        float p = (kg <= qg) ? P_ONE : 0.0f;
                        sacc[at][nt][j] = p;
                        lsum[at][j >> 1] += p;
                    }
        } else {
            #pragma unroll
            for (int at = 0; at < 2; at++)
                #pragma unroll
                for (int nt = 0; nt < 8; nt++) {
                    float2 mv = *(const float2*)(mk + nt * 8 + 2 * tg);
                    float p0 = ex2(sacc[at][nt][0] + mv.x);
                    float p1 = ex2(sacc[at][nt][1] + mv.y);
                    float p2 = ex2(sacc[at][nt][2] + mv.x);
                    float p3 = ex2(sacc[at][nt][3] + mv.y);
                    sacc[at][nt][0] = p0; sacc[at][nt][1] = p1;
                    sacc[at][nt][2] = p2; sacc[at][nt][3] = p3;
                    lsum[at][0] += p0 + p1;
                    lsum[at][1] += p2 + p3;
                }
        }

        // ---- pack P -> fp16 A-fragments (c n-pair == a k-pair; no shuffle) ----
        uint32_t pa[2][4][4];
        #pragma unroll
        for (int at = 0; at < 2; at++)
            #pragma unroll
            for (int ks = 0; ks < 4; ks++) {
                pa[at][ks][0] = packh2(sacc[at][2 * ks][0],     sacc[at][2 * ks][1]);     // (m=g,   k lo)
                pa[at][ks][1] = packh2(sacc[at][2 * ks + 1][0], sacc[at][2 * ks + 1][1]); // (m=g,   k hi)
                pa[at][ks][2] = packh2(sacc[at][2 * ks][2],     sacc[at][2 * ks][3]);     // (m=g+8, k lo)
                pa[at][ks][3] = packh2(sacc[at][2 * ks + 1][2], sacc[at][2 * ks + 1][3]); // (m=g+8, k hi)
            }

        // ---- O += P @ V  (B via ldmatrix.trans from row-major V) ----
        #pragma unroll
        for (int ks = 0; ks < 4; ks++) {
            #pragma unroll
            for (int ntp = 0; ntp < 4; ntp++) {
                uint32_t bm[4];
                ldmx4t(bm, vb_base + (uint32_t)(ks * 16 * PITCHB) + ntp * 32);
                mma16(oacc[0][2 * ntp],     pa[0][ks][0], pa[0][ks][2], pa[0][ks][1], pa[0][ks][3], bm[0], bm[1]);
                mma16(oacc[0][2 * ntp + 1], pa[0][ks][0], pa[0][ks][2], pa[0][ks][1], pa[0][ks][3], bm[2], bm[3]);
                mma16(oacc[1][2 * ntp],     pa[1][ks][0], pa[1][ks][2], pa[1][ks][1], pa[1][ks][3], bm[0], bm[1]);
                mma16(oacc[1][2 * ntp + 1], pa[1][ks][0], pa[1][ks][2], pa[1][ks][1], pa[1][ks][3], bm[2], bm[3]);
            }
        }
    }

    // ---- final l reduction (within quad) + epilogue ----
    #pragma unroll
    for (int at = 0; at < 2; at++)
        #pragma unroll
        for (int rh = 0; rh < 2; rh++) {
            lsum[at][rh] += __shfl_xor_sync(0xffffffffu, lsum[at][rh], 1);
            lsum[at][rh] += __shfl_xor_sync(0xffffffffu, lsum[at][rh], 2);
        }
    #pragma unroll
    for (int at = 0; at < 2; at++)
        #pragma unroll
        for (int rh = 0; rh < 2; rh++) {
            float inv = 1.0f / lsum[at][rh];
            size_t row = (size_t)(qbase + wrow + at * 16 + g + 8 * rh);
            #pragma unroll
            for (int nt = 0; nt < 8; nt++) {
                float2 ov = make_float2(oacc[at][nt][2 * rh] * inv,
                                        oacc[at][nt][2 * rh + 1] * inv);
                *(float2*)(Op + row * DH + nt * 8 + 2 * tg) = ov;
            }
        }
}

extern "C" void kernel_launch(void* const* d_in, const int* in_sizes, int n_in,
                              void* d_out, int out_size)
{
    (void)in_sizes; (void)n_in; (void)out_size;
    const float* Q    = (const float*)d_in[0];
    const float* K    = (const float*)d_in[1];
    const float* V    = (const float*)d_in[2];
    const float* mask = (const float*)d_in[3];
    float* O = (float*)d_out;

    cudaFuncSetAttribute(attn_fp16_kernel,
                         cudaFuncAttributeMaxDynamicSharedMemorySize, SMEM_BYTES);

    dim3 grid(S_LEN / BM, NB * NH);
    attn_fp16_kernel<<<grid, 128, SMEM_BYTES>>>(Q, K, V, mask, O);
}

// round 10
// speedup vs baseline: 2.6070x; 1.9189x over previous
#include <cuda_runtime.h>
#include <cuda_fp16.h>
#include <cstdint>

// CausalAttentionProduct — flash attention, fp16 mma.sync m16n8k16 + ldmatrix.
// R9 = R8 + coalesced staging: each half-warp reads one full 256B row per LDG
// (nL=4 vs 32 before). Same smem layout, same mma structure.
// no-max softmax (SHIFT=14). BM=128, BN=64, 4 warps, 3 CTA/SM.
// Reference quirk: scores[..., -128:, -128:] OVERWRITTEN with (0 if k<=q else -inf).

#define NB 2
#define NH 12
#define S_LEN 4096
#define DH 64
#define BM 128
#define BN 64
#define LOG2E 1.4426950408889634f
#define SHIFT 14.0f
#define P_ONE 6.103515625e-05f   // 2^-14, exact in fp16 (normal)

// half tiles, row pitch 144 bytes (72 halves; 64 data + 8 pad).
#define PITCHB 144
#define OFF_QS 0
#define OFF_KS (OFF_QS + BM * PITCHB)   // 18432
#define OFF_VS (OFF_KS + BN * PITCHB)   // 27648
#define OFF_MK (OFF_VS + BN * PITCHB)   // 36864 (fp32 mask, 64 floats)
#define SMEM_BYTES (OFF_MK + BN * 4)    // 37120 B

extern __shared__ char smem_c[];

__device__ __forceinline__ float ex2(float x) {
    float r;
    asm("ex2.approx.ftz.f32 %0, %1;" : "=f"(r) : "f"(x));
    return r;
}
__device__ __forceinline__ uint32_t s2u(const void* p) {
    uint32_t a;
    asm("{ .reg .u64 t; cvta.to.shared.u64 t, %1; cvt.u32.u64 %0, t; }"
        : "=r"(a) : "l"(p));
    return a;
}
__device__ __forceinline__ uint32_t packh2(float lo, float hi) {
    __half2 h = __floats2half2_rn(lo, hi);
    return *(uint32_t*)&h;
}
__device__ __forceinline__ void ldmx4(uint32_t r[4], uint32_t addr) {
    asm volatile("ldmatrix.sync.aligned.m8n8.x4.shared.b16 {%0,%1,%2,%3}, [%4];"
                 : "=r"(r[0]), "=r"(r[1]), "=r"(r[2]), "=r"(r[3]) : "r"(addr));
}
__device__ __forceinline__ void ldmx4t(uint32_t r[4], uint32_t addr) {
    asm volatile("ldmatrix.sync.aligned.m8n8.x4.trans.shared.b16 {%0,%1,%2,%3}, [%4];"
                 : "=r"(r[0]), "=r"(r[1]), "=r"(r[2]), "=r"(r[3]) : "r"(addr));
}
__device__ __forceinline__ void mma16(float c[4],
                                      uint32_t a0, uint32_t a1, uint32_t a2, uint32_t a3,
                                      uint32_t b0, uint32_t b1) {
    asm volatile(
        "mma.sync.aligned.m16n8k16.row.col.f32.f16.f16.f32 "
        "{%0,%1,%2,%3}, {%4,%5,%6,%7}, {%8,%9}, {%0,%1,%2,%3};"
        : "+f"(c[0]), "+f"(c[1]), "+f"(c[2]), "+f"(c[3])
        : "r"(a0), "r"(a1), "r"(a2), "r"(a3), "r"(b0), "r"(b1));
}

__global__ void __launch_bounds__(128, 3)
attn_fp16_kernel(const float* __restrict__ Q,
                 const float* __restrict__ K,
                 const float* __restrict__ V,
                 const float* __restrict__ mask,
                 float* __restrict__ O)
{
    const int tid  = threadIdx.x;
    const int warp = tid >> 5;
    const int lane = tid & 31;
    const int g    = lane >> 2;
    const int tg   = lane & 3;

    const uint32_t sb = s2u(smem_c);
    float* mk = (float*)(smem_c + OFF_MK);

    const int bh    = blockIdx.y;
    const int b     = bh / NH;
    const int qbase = blockIdx.x * BM;
    const bool qsp  = (qbase == S_LEN - BM);

    const float* Qp = Q + (size_t)bh * S_LEN * DH;
    const float* Kp = K + (size_t)bh * S_LEN * DH;
    const float* Vp = V + (size_t)bh * S_LEN * DH;
    const float* Mp = mask + (size_t)b * S_LEN;
    float* Op = O + (size_t)bh * S_LEN * DH;

    const int wrow = warp * 32;

    // staging lane mapping: each half-warp covers one full 256B row per instr
    const int c4 = lane & 15;   // 16B chunk within row
    const int hl = lane >> 4;   // half-warp

    // ---- ldmatrix lane-address bases ----
    const int lt = lane;
    const int t4 = lt >> 3;             // tile index 0..3
    // QK A: tiles (m0-7,k0-7),(m8-15,k0-7),(m0-7,k8-15),(m8-15,k8-15)
    const uint32_t qa_base = sb + OFF_QS
        + (uint32_t)(wrow + (lt & 7) + ((t4 & 1) * 8)) * PITCHB
        + (uint32_t)((t4 >> 1) * 16);                  // +at*16*PITCHB +ks*32
    // QK B: tiles (n0-7,k0-7),(n0-7,k8-15),(n8-15,k0-7),(n8-15,k8-15)
    const uint32_t kb_base = sb + OFF_KS
        + (uint32_t)(((t4 >> 1) * 8) + (lt & 7)) * PITCHB
        + (uint32_t)((t4 & 1) * 16);                   // +ntp*16*PITCHB +ks*32
    // PV B (trans): tiles (k0-7,n0-7),(k8-15,n0-7),(k0-7,n8-15),(k8-15,n8-15)
    const uint32_t vb_base = sb + OFF_VS
        + (uint32_t)(((t4 & 1) * 8) + (lt & 7)) * PITCHB
        + (uint32_t)((t4 >> 1) * 16);                  // +ks*16*PITCHB +ntp*32

    // ---- stage Q (scaled, fp16), coalesced: 32 rows per warp ----
    {
        const float qs = 0.125f * LOG2E;
        #pragma unroll
        for (int i = 0; i < 16; i++) {
            int m = warp * 32 + hl * 16 + i;
            float4 v = *(const float4*)(Qp + (size_t)(qbase + m) * DH + c4 * 4);
            uint2 u = make_uint2(packh2(v.x * qs, v.y * qs),
                                 packh2(v.z * qs, v.w * qs));
            *(uint2*)(smem_c + OFF_QS + m * PITCHB + c4 * 8) = u;
        }
    }

    float lsum[2][2] = {{0.f, 0.f}, {0.f, 0.f}};
    float oacc[2][8][4];
    #pragma unroll
    for (int at = 0; at < 2; at++)
        #pragma unroll
        for (int nt = 0; nt < 8; nt++)
            #pragma unroll
            for (int j = 0; j < 4; j++) oacc[at][nt][j] = 0.f;

    for (int kt = 0; kt < S_LEN / BN; kt++) {
        const int kbase = kt * BN;

        __syncthreads();

        // ---- stage K, V (fp16) coalesced: 16 rows per warp each ----
        {
            #pragma unroll
            for (int i = 0; i < 8; i++) {
                int n = warp * 16 + hl * 8 + i;
                float4 kv = *(const float4*)(Kp + (size_t)(kbase + n) * DH + c4 * 4);
                *(uint2*)(smem_c + OFF_KS + n * PITCHB + c4 * 8) =
                    make_uint2(packh2(kv.x, kv.y), packh2(kv.z, kv.w));
                float4 vv = *(const float4*)(Vp + (size_t)(kbase + n) * DH + c4 * 4);
                *(uint2*)(smem_c + OFF_VS + n * PITCHB + c4 * 8) =
                    make_uint2(packh2(vv.x, vv.y), packh2(vv.z, vv.w));
            }
            if (tid < 16) {
                float4 mv = *(const float4*)(Mp + kbase + tid * 4);
                mv.x = mv.x * LOG2E - SHIFT;
                mv.y = mv.y * LOG2E - SHIFT;
                mv.z = mv.z * LOG2E - SHIFT;
                mv.w = mv.w * LOG2E - SHIFT;
                *(float4*)(mk + tid * 4) = mv;
            }
        }
        __syncthreads();

        // ---- S = Q @ K^T  (4 k16-steps) ----
        float sacc[2][8][4];
        #pragma unroll
        for (int at = 0; at < 2; at++)
            #pragma unroll
            for (int nt = 0; nt < 8; nt++)
                #pragma unroll
                for (int j = 0; j < 4; j++) sacc[at][nt][j] = 0.f;

        #pragma unroll
        for (int ks = 0; ks < 4; ks++) {
            uint32_t a[2][4];
            ldmx4(a[0], qa_base + ks * 32);
            ldmx4(a[1], qa_base + 16 * PITCHB + ks * 32);
            #pragma unroll
            for (int ntp = 0; ntp < 4; ntp++) {
                uint32_t bm[4];
                ldmx4(bm, kb_base + (uint32_t)(ntp * 16 * PITCHB) + ks * 32);
                mma16(sacc[0][2 * ntp],     a[0][0], a[0][1], a[0][2], a[0][3], bm[0], bm[1]);
                mma16(sacc[0][2 * ntp + 1], a[0][0], a[0][1], a[0][2], a[0][3], bm[2], bm[3]);
                mma16(sacc[1][2 * ntp],     a[1][0], a[1][1], a[1][2], a[1][3], bm[0], bm[1]);
                mma16(sacc[1][2 * ntp + 1], a[1][0], a[1][1], a[1][2], a[1][3], bm[2], bm[3]);
            }
        }

        // ---- softmax (no running max): p = exp2(s + mask*log2e - 14) ----
        if (qsp && kbase >= S_LEN - 128) {
            #pragma unroll
            for (int at = 0; at < 2; at++)
                #pragma unroll
                for (int nt = 0; nt < 8; nt++)
                    #pragma unroll
                    for (int j = 0; j < 4; j++) {
                        int qg = qbase + wrow + at * 16 + g + (j >> 1) * 8;
                        int kg = kbase + nt * 8 + 2 * tg + (j & 1);
                        float p = (kg <= qg) ? P_ONE : 0.0f;
                        sacc[at][nt][j] = p;
                        lsum[at][j >> 1] += p;
                    }
        } else {
            #pragma unroll
            for (int at = 0; at < 2; at++)
                #pragma unroll
                for (int nt = 0; nt < 8; nt++) {
                    float2 mv = *(const float2*)(mk + nt * 8 + 2 * tg);
                    float p0 = ex2(sacc[at][nt][0] + mv.x);
                    float p1 = ex2(sacc[at][nt][1] + mv.y);
                    float p2 = ex2(sacc[at][nt][2] + mv.x);
                    float p3 = ex2(sacc[at][nt][3] + mv.y);
                    sacc[at][nt][0] = p0; sacc[at][nt][1] = p1;
                    sacc[at][nt][2] = p2; sacc[at][nt][3] = p3;
                    lsum[at][0] += p0 + p1;
                    lsum[at][1] += p2 + p3;
                }
        }

        // ---- pack P -> fp16 A-fragments (c n-pair == a k-pair; no shuffle) ----
        uint32_t pa[2][4][4];
        #pragma unroll
        for (int at = 0; at < 2; at++)
            #pragma unroll
            for (int ks = 0; ks < 4; ks++) {
                pa[at][ks][0] = packh2(sacc[at][2 * ks][0],     sacc[at][2 * ks][1]);     // (m=g,   k lo)
                pa[at][ks][1] = packh2(sacc[at][2 * ks + 1][0], sacc[at][2 * ks + 1][1]); // (m=g,   k hi)
                pa[at][ks][2] = packh2(sacc[at][2 * ks][2],     sacc[at][2 * ks][3]);     // (m=g+8, k lo)
                pa[at][ks][3] = packh2(sacc[at][2 * ks + 1][2], sacc[at][2 * ks + 1][3]); // (m=g+8, k hi)
            }

        // ---- O += P @ V  (B via ldmatrix.trans from row-major V) ----
        #pragma unroll
        for (int ks = 0; ks < 4; ks++) {
            #pragma unroll
            for (int ntp = 0; ntp < 4; ntp++) {
                uint32_t bm[4];
                ldmx4t(bm, vb_base + (uint32_t)(ks * 16 * PITCHB) + ntp * 32);
                mma16(oacc[0][2 * ntp],     pa[0][ks][0], pa[0][ks][2], pa[0][ks][1], pa[0][ks][3], bm[0], bm[1]);
                mma16(oacc[0][2 * ntp + 1], pa[0][ks][0], pa[0][ks][2], pa[0][ks][1], pa[0][ks][3], bm[2], bm[3]);
                mma16(oacc[1][2 * ntp],     pa[1][ks][0], pa[1][ks][2], pa[1][ks][1], pa[1][ks][3], bm[0], bm[1]);
                mma16(oacc[1][2 * ntp + 1], pa[1][ks][0], pa[1][ks][2], pa[1][ks][1], pa[1][ks][3], bm[2], bm[3]);
            }
        }
    }

    // ---- final l reduction (within quad) + epilogue ----
    #pragma unroll
    for (int at = 0; at < 2; at++)
        #pragma unroll
        for (int rh = 0; rh < 2; rh++) {
            lsum[at][rh] += __shfl_xor_sync(0xffffffffu, lsum[at][rh], 1);
            lsum[at][rh] += __shfl_xor_sync(0xffffffffu, lsum[at][rh], 2);
        }
    #pragma unroll
    for (int at = 0; at < 2; at++)
        #pragma unroll
        for (int rh = 0; rh < 2; rh++) {
            float inv = 1.0f / lsum[at][rh];
            size_t row = (size_t)(qbase + wrow + at * 16 + g + 8 * rh);
            #pragma unroll
            for (int nt = 0; nt < 8; nt++) {
                float2 ov = make_float2(oacc[at][nt][2 * rh] * inv,
                                        oacc[at][nt][2 * rh + 1] * inv);
                *(float2*)(Op + row * DH + nt * 8 + 2 * tg) = ov;
            }
        }
}

extern "C" void kernel_launch(void* const* d_in, const int* in_sizes, int n_in,
                              void* d_out, int out_size)
{
    (void)in_sizes; (void)n_in; (void)out_size;
    const float* Q    = (const float*)d_in[0];
    const float* K    = (const float*)d_in[1];
    const float* V    = (const float*)d_in[2];
    const float* mask = (const float*)d_in[3];
    float* O = (float*)d_out;

    cudaFuncSetAttribute(attn_fp16_kernel,
                         cudaFuncAttributeMaxDynamicSharedMemorySize, SMEM_BYTES);

    dim3 grid(S_LEN / BM, NB * NH);
    attn_fp16_kernel<<<grid, 128, SMEM_BYTES>>>(Q, K, V, mask, O);
}

// round 11
// speedup vs baseline: 2.6857x; 1.0302x over previous
#include <cuda_runtime.h>
#include <cuda_fp16.h>
#include <cstdint>

// CausalAttentionProduct — flash attention, fp16 mma.sync m16n8k16 + ldmatrix.
// R10 = R9 + (a) one-time prep kernel converting Q(scaled)/K/V to fp16 and
// mask to (m*log2e - 14) in __device__ scratch, (b) cp.async double-buffered
// K/V staging (tile kt+1 issued at top of iter kt, waited at bottom).
// no-max softmax (SHIFT=14). BM=128, BN=64, 4 warps, 3 CTA/SM.
// Reference quirk: scores[..., -128:, -128:] OVERWRITTEN with (0 if k<=q else -inf).

#define NB 2
#define NH 12
#define NBH 24
#define S_LEN 4096
#define DH 64
#define BM 128
#define BN 64
#define NT (S_LEN / BN)
#define LOG2E 1.4426950408889634f
#define SHIFT 14.0f
#define P_ONE 6.103515625e-05f   // 2^-14, exact in fp16 (normal)

// half tiles, row pitch 144 bytes (64 data halves + 8 pad).
#define PITCHB 144
#define OFF_QS 0                         // 128*144 = 18432
#define OFF_KS 18432                     // 2 x 64*144 = 2 x 9216
#define OFF_VS (OFF_KS + 2 * 9216)       // 36864, 2 x 9216
#define OFF_MK (OFF_VS + 2 * 9216)       // 55296, 2 x 256 B
#define SMEM_BYTES (OFF_MK + 512)        // 55808 B

// fp16 scratch (zero-init __device__ globals; no allocation)
__device__ __half g_Qh[(size_t)NBH * S_LEN * DH];
__device__ __half g_Kh[(size_t)NBH * S_LEN * DH];
__device__ __half g_Vh[(size_t)NBH * S_LEN * DH];
__device__ float  g_mkT[(size_t)NB * S_LEN];

extern __shared__ char smem_c[];

__device__ __forceinline__ float ex2(float x) {
    float r;
    asm("ex2.approx.ftz.f32 %0, %1;" : "=f"(r) : "f"(x));
    return r;
}
__device__ __forceinline__ uint32_t s2u(const void* p) {
    uint32_t a;
    asm("{ .reg .u64 t; cvta.to.shared.u64 t, %1; cvt.u32.u64 %0, t; }"
        : "=r"(a) : "l"(p));
    return a;
}
__device__ __forceinline__ uint32_t packh2(float lo, float hi) {
    __half2 h = __floats2half2_rn(lo, hi);
    return *(uint32_t*)&h;
}
__device__ __forceinline__ void cpa16(uint32_t dst, const void* src) {
    asm volatile("cp.async.ca.shared.global [%0], [%1], 16;"
                 :: "r"(dst), "l"(src) : "memory");
}
__device__ __forceinline__ void ldmx4(uint32_t r[4], uint32_t addr) {
    asm volatile("ldmatrix.sync.aligned.m8n8.x4.shared.b16 {%0,%1,%2,%3}, [%4];"
                 : "=r"(r[0]), "=r"(r[1]), "=r"(r[2]), "=r"(r[3]) : "r"(addr));
}
__device__ __forceinline__ void ldmx4t(uint32_t r[4], uint32_t addr) {
    asm volatile("ldmatrix.sync.aligned.m8n8.x4.trans.shared.b16 {%0,%1,%2,%3}, [%4];"
                 : "=r"(r[0]), "=r"(r[1]), "=r"(r[2]), "=r"(r[3]) : "r"(addr));
}
__device__ __forceinline__ void mma16(float c[4],
                                      uint32_t a0, uint32_t a1, uint32_t a2, uint32_t a3,
                                      uint32_t b0, uint32_t b1) {
    asm volatile(
        "mma.sync.aligned.m16n8k16.row.col.f32.f16.f16.f32 "
        "{%0,%1,%2,%3}, {%4,%5,%6,%7}, {%8,%9}, {%0,%1,%2,%3};"
        : "+f"(c[0]), "+f"(c[1]), "+f"(c[2]), "+f"(c[3])
        : "r"(a0), "r"(a1), "r"(a2), "r"(a3), "r"(b0), "r"(b1));
}

// ---- prep: fp32 -> fp16 (Q scaled), 1 float4 per thread ----
__global__ void __launch_bounds__(256)
prep_kernel(const float* __restrict__ Q, const float* __restrict__ K,
            const float* __restrict__ V)
{
    const int t = blockIdx.y;
    const size_t i4 = (size_t)blockIdx.x * 256 + threadIdx.x;
    const float4* src = (const float4*)((t == 0) ? Q : (t == 1) ? K : V);
    uint2* dst = (uint2*)((t == 0) ? g_Qh : (t == 1) ? g_Kh : g_Vh);
    const float sc = (t == 0) ? 0.125f * LOG2E : 1.0f;
    float4 v = src[i4];
    dst[i4] = make_uint2(packh2(v.x * sc, v.y * sc), packh2(v.z * sc, v.w * sc));
}
__global__ void __launch_bounds__(256)
prep_mask_kernel(const float* __restrict__ mask)
{
    const size_t i4 = (size_t)blockIdx.x * 256 + threadIdx.x;
    float4 m = ((const float4*)mask)[i4];
    m.x = m.x * LOG2E - SHIFT;
    m.y = m.y * LOG2E - SHIFT;
    m.z = m.z * LOG2E - SHIFT;
    m.w = m.w * LOG2E - SHIFT;
    ((float4*)g_mkT)[i4] = m;
}

__global__ void __launch_bounds__(128, 3)
attn_fp16_kernel(float* __restrict__ O)
{
    const int tid  = threadIdx.x;
    const int warp = tid >> 5;
    const int lane = tid & 31;
    const int g    = lane >> 2;
    const int tg   = lane & 3;

    const uint32_t sb = s2u(smem_c);

    const int bh    = blockIdx.y;
    const int b     = bh / NH;
    const int qbase = blockIdx.x * BM;
    const bool qsp  = (qbase == S_LEN - BM);

    const __half* Qhp = g_Qh + (size_t)bh * S_LEN * DH;
    const __half* Khp = g_Kh + (size_t)bh * S_LEN * DH;
    const __half* Vhp = g_Vh + (size_t)bh * S_LEN * DH;
    const float*  Mkp = g_mkT + (size_t)b * S_LEN;
    float* Op = O + (size_t)bh * S_LEN * DH;

    const int wrow = warp * 32;

    // ---- ldmatrix lane-address bases ----
    const int t4 = lane >> 3;
    const uint32_t qa_base = sb + OFF_QS
        + (uint32_t)(wrow + (lane & 7) + ((t4 & 1) * 8)) * PITCHB
        + (uint32_t)((t4 >> 1) * 16);
    const uint32_t kb_base0 = sb + OFF_KS
        + (uint32_t)(((t4 >> 1) * 8) + (lane & 7)) * PITCHB
        + (uint32_t)((t4 & 1) * 16);
    const uint32_t vb_base0 = sb + OFF_VS
        + (uint32_t)(((t4 & 1) * 8) + (lane & 7)) * PITCHB
        + (uint32_t)((t4 >> 1) * 16);

    // ---- prologue: cp.async Q tile + K/V/mask tile 0 into buffer 0 ----
    {
        #pragma unroll
        for (int i = 0; i < 8; i++) {
            int linear = tid + 128 * i;          // 0..1023
            int m = linear >> 3, c = linear & 7;
            cpa16(sb + OFF_QS + m * PITCHB + c * 16,
                  Qhp + (size_t)(qbase + m) * DH + c * 8);
        }
        #pragma unroll
        for (int i = 0; i < 4; i++) {
            int linear = tid + 128 * i;          // 0..511
            int n = linear >> 3, c = linear & 7;
            cpa16(sb + OFF_KS + n * PITCHB + c * 16, Khp + (size_t)n * DH + c * 8);
            cpa16(sb + OFF_VS + n * PITCHB + c * 16, Vhp + (size_t)n * DH + c * 8);
        }
        if (tid < 16) cpa16(sb + OFF_MK + tid * 16, Mkp + tid * 4);
        asm volatile("cp.async.commit_group;" ::: "memory");
        asm volatile("cp.async.wait_group 0;" ::: "memory");
        __syncthreads();
    }

    float lsum[2][2] = {{0.f, 0.f}, {0.f, 0.f}};
    float oacc[2][8][4];
    #pragma unroll
    for (int at = 0; at < 2; at++)
        #pragma unroll
        for (int nt = 0; nt < 8; nt++)
            #pragma unroll
            for (int j = 0; j < 4; j++) oacc[at][nt][j] = 0.f;

    for (int kt = 0; kt < NT; kt++) {
        const int kbase = kt * BN;
        const int buf = kt & 1;

        // ---- prefetch tile kt+1 into the other buffer ----
        if (kt + 1 < NT) {
            const int nb = buf ^ 1;
            const size_t nk = (size_t)(kbase + BN) * DH;
            #pragma unroll
            for (int i = 0; i < 4; i++) {
                int linear = tid + 128 * i;
                int n = linear >> 3, c = linear & 7;
                cpa16(sb + OFF_KS + nb * 9216 + n * PITCHB + c * 16,
                      Khp + nk + (size_t)n * DH + c * 8);
                cpa16(sb + OFF_VS + nb * 9216 + n * PITCHB + c * 16,
                      Vhp + nk + (size_t)n * DH + c * 8);
            }
            if (tid < 16)
                cpa16(sb + OFF_MK + nb * 256 + tid * 16, Mkp + kbase + BN + tid * 4);
        }
        asm volatile("cp.async.commit_group;" ::: "memory");

        const uint32_t kbb = kb_base0 + buf * 9216;
        const uint32_t vbb = vb_base0 + buf * 9216;
        const float* mkp = (const float*)(smem_c + OFF_MK + buf * 256);

        // ---- S = Q @ K^T  (4 k16-steps) ----
        float sacc[2][8][4];
        #pragma unroll
        for (int at = 0; at < 2; at++)
            #pragma unroll
            for (int nt = 0; nt < 8; nt++)
                #pragma unroll
                for (int j = 0; j < 4; j++) sacc[at][nt][j] = 0.f;

        #pragma unroll
        for (int ks = 0; ks < 4; ks++) {
            uint32_t a[2][4];
            ldmx4(a[0], qa_base + ks * 32);
            ldmx4(a[1], qa_base + 16 * PITCHB + ks * 32);
            #pragma unroll
            for (int ntp = 0; ntp < 4; ntp++) {
                uint32_t bm[4];
                ldmx4(bm, kbb + (uint32_t)(ntp * 16 * PITCHB) + ks * 32);
                mma16(sacc[0][2 * ntp],     a[0][0], a[0][1], a[0][2], a[0][3], bm[0], bm[1]);
                mma16(sacc[0][2 * ntp + 1], a[0][0], a[0][1], a[0][2], a[0][3], bm[2], bm[3]);
                mma16(sacc[1][2 * ntp],     a[1][0], a[1][1], a[1][2], a[1][3], bm[0], bm[1]);
                mma16(sacc[1][2 * ntp + 1], a[1][0], a[1][1], a[1][2], a[1][3], bm[2], bm[3]);
            }
        }

        // ---- softmax (no running max): p = exp2(s + mk) ----
        if (qsp && kbase >= S_LEN - 128) {
            #pragma unroll
            for (int at = 0; at < 2; at++)
                #pragma unroll
                for (int nt = 0; nt < 8; nt++)
                    #pragma unroll
                    for (int j = 0; j < 4; j++) {
                        int qg = qbase + wrow + at * 16 + g + (j >> 1) * 8;
                        int kg = kbase + nt * 8 + 2 * tg + (j & 1);
                        float p = (kg <= qg) ? P_ONE : 0.0f;
                        sacc[at][nt][j] = p;
                        lsum[at][j >> 1] += p;
                    }
        } else {
            #pragma unroll
            for (int at = 0; at < 2; at++)
                #pragma unroll
                for (int nt = 0; nt < 8; nt++) {
                    float2 mv = *(const float2*)(mkp + nt * 8 + 2 * tg);
                    float p0 = ex2(sacc[at][nt][0] + mv.x);
                    float p1 = ex2(sacc[at][nt][1] + mv.y);
                    float p2 = ex2(sacc[at][nt][2] + mv.x);
                    float p3 = ex2(sacc[at][nt][3] + mv.y);
                    sacc[at][nt][0] = p0; sacc[at][nt][1] = p1;
                    sacc[at][nt][2] = p2; sacc[at][nt][3] = p3;
                    lsum[at][0] += p0 + p1;
                    lsum[at][1] += p2 + p3;
                }
        }

        // ---- pack P -> fp16 A-fragments ----
        uint32_t pa[2][4][4];
        #pragma unroll
        for (int at = 0; at < 2; at++)
            #pragma unroll
            for (int ks = 0; ks < 4; ks++) {
                pa[at][ks][0] = packh2(sacc[at][2 * ks][0],     sacc[at][2 * ks][1]);
                pa[at][ks][1] = packh2(sacc[at][2 * ks + 1][0], sacc[at][2 * ks + 1][1]);
                pa[at][ks][2] = packh2(sacc[at][2 * ks][2],     sacc[at][2 * ks][3]);
                pa[at][ks][3] = packh2(sacc[at][2 * ks + 1][2], sacc[at][2 * ks + 1][3]);
            }

        // ---- O += P @ V ----
        #pragma unroll
        for (int ks = 0; ks < 4; ks++) {
            #pragma unroll
            for (int ntp = 0; ntp < 4; ntp++) {
                uint32_t bm[4];
                ldmx4t(bm, vbb + (uint32_t)(ks * 16 * PITCHB) + ntp * 32);
                mma16(oacc[0][2 * ntp],     pa[0][ks][0], pa[0][ks][2], pa[0][ks][1], pa[0][ks][3], bm[0], bm[1]);
                mma16(oacc[0][2 * ntp + 1], pa[0][ks][0], pa[0][ks][2], pa[0][ks][1], pa[0][ks][3], bm[2], bm[3]);
                mma16(oacc[1][2 * ntp],     pa[1][ks][0], pa[1][ks][2], pa[1][ks][1], pa[1][ks][3], bm[0], bm[1]);
                mma16(oacc[1][2 * ntp + 1], pa[1][ks][0], pa[1][ks][2], pa[1][ks][1], pa[1][ks][3], bm[2], bm[3]);
            }
        }

        // next tile's cp.asyncs have had the whole compute phase to land
        asm volatile("cp.async.wait_group 0;" ::: "memory");
        __syncthreads();
    }

    // ---- final l reduction (within quad) + epilogue ----
    #pragma unroll
    for (int at = 0; at < 2; at++)
        #pragma unroll
        for (int rh = 0; rh < 2; rh++) {
            lsum[at][rh] += __shfl_xor_sync(0xffffffffu, lsum[at][rh], 1);
            lsum[at][rh] += __shfl_xor_sync(0xffffffffu, lsum[at][rh], 2);
        }
    #pragma unroll
    for (int at = 0; at < 2; at++)
        #pragma unroll
        for (int rh = 0; rh < 2; rh++) {
            float inv = 1.0f / lsum[at][rh];
            size_t row = (size_t)(qbase + wrow + at * 16 + g + 8 * rh);
            #pragma unroll
            for (int nt = 0; nt < 8; nt++) {
                float2 ov = make_float2(oacc[at][nt][2 * rh] * inv,
                                        oacc[at][nt][2 * rh + 1] * inv);
                *(float2*)(Op + row * DH + nt * 8 + 2 * tg) = ov;
            }
        }
}

extern "C" void kernel_launch(void* const* d_in, const int* in_sizes, int n_in,
                              void* d_out, int out_size)
{
    (void)in_sizes; (void)n_in; (void)out_size;
    const float* Q    = (const float*)d_in[0];
    const float* K    = (const float*)d_in[1];
    const float* V    = (const float*)d_in[2];
    const float* mask = (const float*)d_in[3];
    float* O = (float*)d_out;

    // prep: fp32 -> fp16 scratch (Q scaled), mask transform
    {
        const size_t n4 = (size_t)NBH * S_LEN * DH / 4;   // float4 per tensor
        dim3 pg((unsigned)(n4 / 256), 3);
        prep_kernel<<<pg, 256>>>(Q, K, V);
        prep_mask_kernel<<<(NB * S_LEN / 4) / 256, 256>>>(mask);
    }

    cudaFuncSetAttribute(attn_fp16_kernel,
                         cudaFuncAttributeMaxDynamicSharedMemorySize, SMEM_BYTES);
    dim3 grid(S_LEN / BM, NBH);
    attn_fp16_kernel<<<grid, 128, SMEM_BYTES>>>(O);
}